// round 1
// baseline (speedup 1.0000x reference)
#include <cuda_runtime.h>
#include <cstdint>

#define NN      20000
#define EE      320000
#define IN_DIM  256
#define H0      4
#define D0      128
#define F1      512     // H0*D0
#define OUTF    64

// ---------------- device scratch (allocation-free contract) ----------------
__device__ float g_feat1[(size_t)NN * F1];   // x @ W1            [N,512]
__device__ float g_h    [(size_t)NN * F1];   // layer-1 output    [N,512]
__device__ float g_feat2[(size_t)NN * OUTF]; // h @ W2            [N,64]
__device__ float g_el1[NN * H0];
__device__ float g_er1[NN * H0];
__device__ float g_el2[NN];
__device__ float g_er2[NN];
__device__ int   g_deg[NN];
__device__ int   g_rowptr[NN + 1];
__device__ int   g_csr_src[EE];

// ---------------- CSR build ----------------
__global__ void zero_deg_kernel() {
    int i = blockIdx.x * blockDim.x + threadIdx.x;
    if (i < NN) g_deg[i] = 0;
}

__global__ void count_deg_kernel(const int* __restrict__ dst) {
    int i = blockIdx.x * blockDim.x + threadIdx.x;
    if (i < EE) atomicAdd(&g_deg[dst[i]], 1);
}

// single-block exclusive scan of g_deg -> g_rowptr, reset g_deg to 0
__global__ void scan_kernel() {
    __shared__ int sbuf[1024];
    __shared__ int carry;
    int t = threadIdx.x;
    if (t == 0) carry = 0;
    __syncthreads();
    for (int base = 0; base < NN; base += 1024) {
        int i = base + t;
        int v = (i < NN) ? g_deg[i] : 0;
        sbuf[t] = v;
        __syncthreads();
        for (int off = 1; off < 1024; off <<= 1) {
            int a = (t >= off) ? sbuf[t - off] : 0;
            __syncthreads();
            sbuf[t] += a;
            __syncthreads();
        }
        if (i < NN) g_rowptr[i] = carry + sbuf[t] - v;
        __syncthreads();
        if (t == 0) carry += sbuf[1023];
        __syncthreads();
    }
    if (t == 0) g_rowptr[NN] = carry;
    for (int i = t; i < NN; i += 1024) g_deg[i] = 0;
}

__global__ void scatter_kernel(const int* __restrict__ src, const int* __restrict__ dst) {
    int i = blockIdx.x * blockDim.x + threadIdx.x;
    if (i >= EE) return;
    int d = dst[i];
    int pos = g_rowptr[d] + atomicAdd(&g_deg[d], 1);
    g_csr_src[pos] = src[i];
}

// ---------------- SGEMM: C[M,Nc] = A[M,K] @ B[K,Nc] (row-major) ----------------
// BM=64 BN=64 BK=16, 256 threads, 4x4 per thread. Nc % 64 == 0, K % 16 == 0.
__global__ void sgemm_kernel(const float* __restrict__ A, const float* __restrict__ B,
                             float* __restrict__ C, int M, int Nc, int K) {
    __shared__ float As[16][64];
    __shared__ float Bs[16][64];
    const int tid = threadIdx.x;
    const int tx = tid & 15;         // 0..15 -> N
    const int ty = tid >> 4;         // 0..15 -> M
    const int row0 = blockIdx.y * 64;
    const int col0 = blockIdx.x * 64;

    const int aRow = tid >> 2;           // 0..63
    const int aCol = (tid & 3) << 2;     // 0,4,8,12
    const int bRow = tid >> 4;           // 0..15
    const int bCol = (tid & 15) << 2;    // 0..60

    float acc[4][4] = {};

    for (int k0 = 0; k0 < K; k0 += 16) {
        float4 av = make_float4(0.f, 0.f, 0.f, 0.f);
        int gr = row0 + aRow;
        if (gr < M) av = *(const float4*)(A + (size_t)gr * K + k0 + aCol);
        As[aCol + 0][aRow] = av.x;
        As[aCol + 1][aRow] = av.y;
        As[aCol + 2][aRow] = av.z;
        As[aCol + 3][aRow] = av.w;

        float4 bv = *(const float4*)(B + (size_t)(k0 + bRow) * Nc + col0 + bCol);
        *(float4*)&Bs[bRow][bCol] = bv;
        __syncthreads();

#pragma unroll
        for (int k = 0; k < 16; k++) {
            float ra[4], rb[4];
#pragma unroll
            for (int i = 0; i < 4; i++) ra[i] = As[k][ty * 4 + i];
#pragma unroll
            for (int j = 0; j < 4; j++) rb[j] = Bs[k][tx * 4 + j];
#pragma unroll
            for (int i = 0; i < 4; i++)
#pragma unroll
                for (int j = 0; j < 4; j++) acc[i][j] += ra[i] * rb[j];
        }
        __syncthreads();
    }

#pragma unroll
    for (int i = 0; i < 4; i++) {
        int r = row0 + ty * 4 + i;
        if (r >= M) continue;
        *(float4*)(C + (size_t)r * Nc + col0 + tx * 4) =
            make_float4(acc[i][0], acc[i][1], acc[i][2], acc[i][3]);
    }
}

// ---------------- el/er projections: one warp per (node, head) ----------------
__global__ void elr_kernel(const float* __restrict__ feat, const float* __restrict__ al,
                           const float* __restrict__ ar, float* __restrict__ el,
                           float* __restrict__ er, int H, int D) {
    int warp = (blockIdx.x * blockDim.x + threadIdx.x) >> 5;
    int lane = threadIdx.x & 31;
    if (warp >= NN * H) return;
    int n = warp / H, h = warp - n * H;
    const float* f = feat + (size_t)n * H * D + h * D;
    const float* pl = al + h * D;
    const float* pr = ar + h * D;
    float sl = 0.f, sr = 0.f;
    for (int d = lane; d < D; d += 32) {
        float v = f[d];
        sl += v * pl[d];
        sr += v * pr[d];
    }
#pragma unroll
    for (int o = 16; o > 0; o >>= 1) {
        sl += __shfl_xor_sync(0xffffffffu, sl, o);
        sr += __shfl_xor_sync(0xffffffffu, sr, o);
    }
    if (lane == 0) { el[n * H + h] = sl; er[n * H + h] = sr; }
}

__device__ __forceinline__ float leaky(float e) { return e > 0.f ? e : 0.2f * e; }

// ---------------- layer-1 aggregation: one warp per dst node ----------------
// edge softmax over 4 heads, gather feat1[src] (512f), + bias, ELU -> g_h
__global__ void agg1_kernel(const float* __restrict__ b1) {
    int node = (blockIdx.x * blockDim.x + threadIdx.x) >> 5;
    int lane = threadIdx.x & 31;
    if (node >= NN) return;
    int beg = g_rowptr[node], end = g_rowptr[node + 1];

    int hh = lane & 3;
    float er_hh = g_er1[node * 4 + hh];

    // pass 1: per-head max  (8 lanes per head, stride 8 over edges)
    float m = -INFINITY;
    for (int j = beg + (lane >> 2); j < end; j += 8) {
        int s = g_csr_src[j];
        m = fmaxf(m, leaky(g_el1[s * 4 + hh] + er_hh));
    }
#pragma unroll
    for (int o = 4; o < 32; o <<= 1) m = fmaxf(m, __shfl_xor_sync(0xffffffffu, m, o));

    // pass 2: per-head sum of exp
    float ssum = 0.f;
    for (int j = beg + (lane >> 2); j < end; j += 8) {
        int s = g_csr_src[j];
        ssum += __expf(leaky(g_el1[s * 4 + hh] + er_hh) - m);
    }
#pragma unroll
    for (int o = 4; o < 32; o <<= 1) ssum += __shfl_xor_sync(0xffffffffu, ssum, o);

    // pass 3: weighted gather. lane owns 16 contiguous feats -> head = lane>>3
    int myhead = lane >> 3;
    float m_h = __shfl_sync(0xffffffffu, m, myhead);      // lanes 0..3 hold heads 0..3
    float s_h = __shfl_sync(0xffffffffu, ssum, myhead);
    float er_mh = g_er1[node * 4 + myhead];

    float acc[16];
#pragma unroll
    for (int q = 0; q < 16; q++) acc[q] = 0.f;

    for (int j = beg; j < end; j++) {
        int s = g_csr_src[j];
        float e = leaky(g_el1[s * 4 + myhead] + er_mh);
        float alpha = __expf(e - m_h) / s_h;
        const float4* fp = (const float4*)(g_feat1 + (size_t)s * F1 + lane * 16);
#pragma unroll
        for (int q = 0; q < 4; q++) {
            float4 v = fp[q];
            acc[q * 4 + 0] += alpha * v.x;
            acc[q * 4 + 1] += alpha * v.y;
            acc[q * 4 + 2] += alpha * v.z;
            acc[q * 4 + 3] += alpha * v.w;
        }
    }

    // bias + ELU + store
    float* ho = g_h + (size_t)node * F1 + lane * 16;
#pragma unroll
    for (int q = 0; q < 4; q++) {
        float4 o4;
        float v;
        v = acc[q * 4 + 0] + b1[lane * 16 + q * 4 + 0]; o4.x = v > 0.f ? v : expm1f(v);
        v = acc[q * 4 + 1] + b1[lane * 16 + q * 4 + 1]; o4.y = v > 0.f ? v : expm1f(v);
        v = acc[q * 4 + 2] + b1[lane * 16 + q * 4 + 2]; o4.z = v > 0.f ? v : expm1f(v);
        v = acc[q * 4 + 3] + b1[lane * 16 + q * 4 + 3]; o4.w = v > 0.f ? v : expm1f(v);
        *(float4*)(ho + q * 4) = o4;
    }
}

// ---------------- layer-2 aggregation: one warp per dst node, H=1 D=64 ----------------
__global__ void agg2_kernel(const float* __restrict__ b2, float* __restrict__ out) {
    int node = (blockIdx.x * blockDim.x + threadIdx.x) >> 5;
    int lane = threadIdx.x & 31;
    if (node >= NN) return;
    int beg = g_rowptr[node], end = g_rowptr[node + 1];

    float er_n = g_er2[node];

    float m = -INFINITY;
    for (int j = beg + lane; j < end; j += 32)
        m = fmaxf(m, leaky(g_el2[g_csr_src[j]] + er_n));
#pragma unroll
    for (int o = 16; o > 0; o >>= 1) m = fmaxf(m, __shfl_xor_sync(0xffffffffu, m, o));

    float ssum = 0.f;
    for (int j = beg + lane; j < end; j += 32)
        ssum += __expf(leaky(g_el2[g_csr_src[j]] + er_n) - m);
#pragma unroll
    for (int o = 16; o > 0; o >>= 1) ssum += __shfl_xor_sync(0xffffffffu, ssum, o);

    float acc0 = 0.f, acc1 = 0.f;
    for (int j = beg; j < end; j++) {
        int s = g_csr_src[j];
        float e = leaky(g_el2[s] + er_n);
        float alpha = __expf(e - m) / ssum;
        float2 v = *(const float2*)(g_feat2 + (size_t)s * OUTF + lane * 2);
        acc0 += alpha * v.x;
        acc1 += alpha * v.y;
    }
    float2 o2;
    o2.x = acc0 + b2[lane * 2 + 0];
    o2.y = acc1 + b2[lane * 2 + 1];
    *(float2*)(out + (size_t)node * OUTF + lane * 2) = o2;
}

// ---------------- host launch ----------------
extern "C" void kernel_launch(void* const* d_in, const int* in_sizes, int n_in,
                              void* d_out, int out_size) {
    const float* x   = (const float*)d_in[0];
    const int*   src = (const int*)d_in[1];
    const int*   dst = (const int*)d_in[2];
    const float* W1  = (const float*)d_in[3];
    const float* al1 = (const float*)d_in[4];
    const float* ar1 = (const float*)d_in[5];
    const float* b1  = (const float*)d_in[6];
    const float* W2  = (const float*)d_in[7];
    const float* al2 = (const float*)d_in[8];
    const float* ar2 = (const float*)d_in[9];
    const float* b2  = (const float*)d_in[10];
    float* out = (float*)d_out;

    void *p_feat1, *p_h, *p_feat2, *p_el1, *p_er1, *p_el2, *p_er2;
    cudaGetSymbolAddress(&p_feat1, g_feat1);
    cudaGetSymbolAddress(&p_h, g_h);
    cudaGetSymbolAddress(&p_feat2, g_feat2);
    cudaGetSymbolAddress(&p_el1, g_el1);
    cudaGetSymbolAddress(&p_er1, g_er1);
    cudaGetSymbolAddress(&p_el2, g_el2);
    cudaGetSymbolAddress(&p_er2, g_er2);

    // CSR build
    zero_deg_kernel<<<(NN + 255) / 256, 256>>>();
    count_deg_kernel<<<(EE + 255) / 256, 256>>>(dst);
    scan_kernel<<<1, 1024>>>();
    scatter_kernel<<<(EE + 255) / 256, 256>>>(src, dst);

    // Layer 1: feat1 = x @ W1  (M=20000, Nc=512, K=256)
    {
        dim3 grid(F1 / 64, (NN + 63) / 64);
        sgemm_kernel<<<grid, 256>>>(x, W1, (float*)p_feat1, NN, F1, IN_DIM);
    }
    {
        int warps = NN * H0;
        elr_kernel<<<(warps * 32 + 255) / 256, 256>>>((const float*)p_feat1, al1, ar1,
                                                      (float*)p_el1, (float*)p_er1, H0, D0);
    }
    agg1_kernel<<<(NN * 32 + 255) / 256, 256>>>(b1);

    // Layer 2: feat2 = h @ W2  (M=20000, Nc=64, K=512)
    {
        dim3 grid(OUTF / 64, (NN + 63) / 64);
        sgemm_kernel<<<grid, 256>>>((const float*)p_h, W2, (float*)p_feat2, NN, OUTF, F1);
    }
    {
        int warps = NN * 1;
        elr_kernel<<<(warps * 32 + 255) / 256, 256>>>((const float*)p_feat2, al2, ar2,
                                                      (float*)p_el2, (float*)p_er2, 1, OUTF);
    }
    agg2_kernel<<<(NN * 32 + 255) / 256, 256>>>(b2, out);
}